// round 15
// baseline (speedup 1.0000x reference)
#include <cuda_runtime.h>
#include <cuda_fp16.h>
#include <cstdint>

#define NN 100000
#define NE 1600000
#define DF 128
#define NC 64
#define SCAN_BLK 98   // ceil(100000/1024)

// Scratch (__device__ globals per allocation-free rule)
__device__ __half g_yh[NN * NC];    // y then y' = y*dinv, fp16 (12.8MB)
__device__ float g_dinv[NN];
__device__ int   g_cnt[NN];         // edge-dst histogram (deg - 1)
__device__ int   g_incl[NN];        // inclusive scan within 1024-chunk
__device__ int   g_bsum[128];       // per-chunk sums
__device__ int   g_rowstart[NN];    // CSR row pointer (exclusive prefix)
__device__ int   g_cursor[NN];      // scatter cursors
__device__ int   g_ssrc[NE];        // edge sources sorted by dst

// Streams/events for fork-join graph parallelism (lazy init on first call,
// which is the harness correctness run preceding graph capture).
static cudaStream_t g_side = nullptr;
static cudaEvent_t g_evFork = nullptr, g_evDinv = nullptr, g_evJoin = nullptr;

__device__ __forceinline__ uint32_t smem_to_u32(const void* p) {
    uint32_t a;
    asm("{ .reg .u64 t; cvta.to.shared.u64 t, %1; cvt.u32.u64 %0, t; }"
        : "=r"(a) : "l"(p));
    return a;
}
__device__ __forceinline__ uint32_t h2_to_u32(__half2 h) {
    return *reinterpret_cast<uint32_t*>(&h);
}
__device__ __forceinline__ __half2 u32_to_h2(uint32_t u) {
    return *reinterpret_cast<__half2*>(&u);
}

// ---------------------------------------------------------------------------
// 1) zero histogram
// ---------------------------------------------------------------------------
__global__ void zero_kernel() {
    int i = blockIdx.x * blockDim.x + threadIdx.x;
    if (i < NN) g_cnt[i] = 0;
}

// 2) histogram over edge destinations
__global__ void hist_kernel(const int* __restrict__ dst) {
    int e = blockIdx.x * blockDim.x + threadIdx.x;
    if (e < NE) atomicAdd(&g_cnt[dst[e]], 1);
}

// 2b) dinv = rsqrt(deg)  (needs only the histogram, runs before the scans)
__global__ void dinv_kernel() {
    int i = blockIdx.x * blockDim.x + threadIdx.x;
    if (i < NN) g_dinv[i] = rsqrtf((float)g_cnt[i] + 1.0f);
}

// 3a) inclusive scan within each 1024-chunk (warp-shfl)
__global__ __launch_bounds__(1024) void scan_a_kernel() {
    __shared__ int wsum[32];
    int t = threadIdx.x;
    int lane = t & 31, wid = t >> 5;
    int gid = blockIdx.x * 1024 + t;
    int inc = (gid < NN) ? g_cnt[gid] : 0;
#pragma unroll
    for (int off = 1; off < 32; off <<= 1) {
        int u = __shfl_up_sync(0xffffffffu, inc, off);
        if (lane >= off) inc += u;
    }
    if (lane == 31) wsum[wid] = inc;
    __syncthreads();
    if (wid == 0) {
        int s2 = wsum[lane];
#pragma unroll
        for (int off = 1; off < 32; off <<= 1) {
            int u = __shfl_up_sync(0xffffffffu, s2, off);
            if (lane >= off) s2 += u;
        }
        wsum[lane] = s2;
    }
    __syncthreads();
    if (wid > 0) inc += wsum[wid - 1];
    if (gid < NN) g_incl[gid] = inc;
    if (t == 1023) g_bsum[blockIdx.x] = inc;
}

// 3b) finalize (fused chunk-sum prefix): row_start, cursor
__global__ __launch_bounds__(256) void scan_c_kernel() {
    __shared__ int sbase;
    int t = threadIdx.x;
    int bl = blockIdx.x >> 2;
    if (t < 32) {
        int acc = 0;
        for (int q = t; q < bl; q += 32) acc += g_bsum[q];
#pragma unroll
        for (int o = 16; o; o >>= 1) acc += __shfl_xor_sync(0xffffffffu, acc, o);
        if (t == 0) sbase = acc;
    }
    __syncthreads();
    int gid = blockIdx.x * 256 + t;
    if (gid >= NN) return;
    int c = g_cnt[gid];
    int rs = sbase + g_incl[gid] - c;
    g_rowstart[gid] = rs;
    g_cursor[gid] = rs;
}

// 4) scatter: sort edge sources by dst bucket
__global__ void scatter_kernel(const int* __restrict__ src,
                               const int* __restrict__ dst) {
    int e = blockIdx.x * blockDim.x + threadIdx.x;
    if (e >= NE) return;
    int d = dst[e];
    int pos = atomicAdd(&g_cursor[d], 1);
    g_ssrc[pos] = src[e];
}

// ---------------------------------------------------------------------------
// 5) GEMM: y[N,64] = x[N,128] @ W^T  (fma.rn.f32x2), epilogue converts to fp16
// ---------------------------------------------------------------------------
__global__ __launch_bounds__(128) void gemm3_kernel(const float* __restrict__ x,
                                                    const float* __restrict__ W) {
    __shared__ float Wsm[DF * NC];   // [k][c], 32KB
    __shared__ float Xs[256 * 12];   // 12KB staged x
    int t = threadIdx.x;

    for (int i = t; i < DF * NC; i += 128) {
        int k = i >> 6, c = i & 63;
        Wsm[k * NC + c] = W[c * DF + k];
    }

    int w = t >> 5, l = t & 31;
    int ch = w & 1, pair = w >> 1;
    int rbase = blockIdx.x * 256;
    uint32_t w_base = smem_to_u32(Wsm) + (uint32_t)ch * 128;

    unsigned long long acc[4][16];
#pragma unroll
    for (int rr = 0; rr < 4; rr++)
#pragma unroll
        for (int q = 0; q < 16; q++) acc[rr][q] = 0ULL;

    const float4* x4 = reinterpret_cast<const float4*>(x);

    float4 pre[4];
#pragma unroll
    for (int i2 = 0; i2 < 4; i2++) {
        int idx = t + i2 * 128;
        int row = idx >> 1, half = idx & 1;
        int gr = rbase + row;
        pre[i2] = (gr < NN) ? x4[(size_t)gr * 32 + half]
                            : make_float4(0.f, 0.f, 0.f, 0.f);
    }

    for (int cc = 0; cc < 16; cc++) {
#pragma unroll
        for (int i2 = 0; i2 < 4; i2++) {
            int idx = t + i2 * 128;
            int row = idx >> 1, half = idx & 1;
            *reinterpret_cast<float4*>(Xs + row * 12 + half * 4) = pre[i2];
        }
        __syncthreads();

        if (cc < 15) {
#pragma unroll
            for (int i2 = 0; i2 < 4; i2++) {
                int idx = t + i2 * 128;
                int row = idx >> 1, half = idx & 1;
                int gr = rbase + row;
                pre[i2] = (gr < NN) ? x4[(size_t)gr * 32 + (cc + 1) * 2 + half]
                                    : make_float4(0.f, 0.f, 0.f, 0.f);
            }
        }

        float af[4][8];
#pragma unroll
        for (int rr = 0; rr < 4; rr++) {
            int rl = pair * 128 + 32 * rr + l;
            float4 v0 = *reinterpret_cast<const float4*>(Xs + rl * 12);
            float4 v1 = *reinterpret_cast<const float4*>(Xs + rl * 12 + 4);
            af[rr][0] = v0.x; af[rr][1] = v0.y; af[rr][2] = v0.z; af[rr][3] = v0.w;
            af[rr][4] = v1.x; af[rr][5] = v1.y; af[rr][6] = v1.z; af[rr][7] = v1.w;
        }

#pragma unroll
        for (int k = 0; k < 8; k++) {
            unsigned long long bm[4];
#pragma unroll
            for (int rr = 0; rr < 4; rr++)
                asm("mov.b64 %0, {%1, %1};" : "=l"(bm[rr]) : "f"(af[rr][k]));
            uint32_t rowa = w_base + (uint32_t)(cc * 8 + k) * (NC * 4);
#pragma unroll
            for (int q = 0; q < 8; q++) {
                unsigned long long w0, w1;
                asm("ld.shared.v2.b64 {%0, %1}, [%2];"
                    : "=l"(w0), "=l"(w1) : "r"(rowa + q * 16));
#pragma unroll
                for (int rr = 0; rr < 4; rr++) {
                    asm("fma.rn.f32x2 %0, %1, %2, %0;" : "+l"(acc[rr][2*q])   : "l"(bm[rr]), "l"(w0));
                    asm("fma.rn.f32x2 %0, %1, %2, %0;" : "+l"(acc[rr][2*q+1]) : "l"(bm[rr]), "l"(w1));
                }
            }
        }
        __syncthreads();
    }

#pragma unroll
    for (int rr = 0; rr < 4; rr++) {
        int r = rbase + pair * 128 + 32 * rr + l;
        if (r >= NN) continue;
        uint4* yo = reinterpret_cast<uint4*>(
            reinterpret_cast<char*>(g_yh) + (size_t)r * (NC * 2) + ch * 64);
#pragma unroll
        for (int q = 0; q < 4; q++) {
            float2 f0, f1, f2, f3;
            asm("mov.b64 {%0, %1}, %2;" : "=f"(f0.x), "=f"(f0.y) : "l"(acc[rr][4*q]));
            asm("mov.b64 {%0, %1}, %2;" : "=f"(f1.x), "=f"(f1.y) : "l"(acc[rr][4*q+1]));
            asm("mov.b64 {%0, %1}, %2;" : "=f"(f2.x), "=f"(f2.y) : "l"(acc[rr][4*q+2]));
            asm("mov.b64 {%0, %1}, %2;" : "=f"(f3.x), "=f"(f3.y) : "l"(acc[rr][4*q+3]));
            uint4 o;
            o.x = h2_to_u32(__floats2half2_rn(f0.x, f0.y));
            o.y = h2_to_u32(__floats2half2_rn(f1.x, f1.y));
            o.z = h2_to_u32(__floats2half2_rn(f2.x, f2.y));
            o.w = h2_to_u32(__floats2half2_rn(f3.x, f3.y));
            yo[q] = o;
        }
    }
}

// ---------------------------------------------------------------------------
// 5b) scale pass: y' = y * dinv[row]  (fp32 math, fp16 storage)
// ---------------------------------------------------------------------------
__global__ __launch_bounds__(256) void scale_kernel() {
    int i = blockIdx.x * blockDim.x + threadIdx.x;
    if (i >= NN * NC / 8) return;
    float d = g_dinv[i >> 3];
    uint4* p = reinterpret_cast<uint4*>(g_yh) + i;
    uint4 u = *p;
    float2 a = __half22float2(u32_to_h2(u.x));
    float2 b = __half22float2(u32_to_h2(u.y));
    float2 c = __half22float2(u32_to_h2(u.z));
    float2 e = __half22float2(u32_to_h2(u.w));
    u.x = h2_to_u32(__floats2half2_rn(a.x * d, a.y * d));
    u.y = h2_to_u32(__floats2half2_rn(b.x * d, b.y * d));
    u.z = h2_to_u32(__floats2half2_rn(c.x * d, c.y * d));
    u.w = h2_to_u32(__floats2half2_rn(e.x * d, e.y * d));
    *p = u;
}

// ---------------------------------------------------------------------------
// 6) fused gather + log_softmax, warp per node, prescaled fp16 y'.
//    Per edge: only shfl(s) + one 128B line gather. No dinv gather, no FMUL.
// ---------------------------------------------------------------------------
__global__ __launch_bounds__(256) void gather_out_kernel(const float* __restrict__ b,
                                                         float* __restrict__ out) {
    int node = (blockIdx.x * 256 + threadIdx.x) >> 5;
    int l = threadIdx.x & 31;
    if (node >= NN) return;
    int half = l >> 4, chunk = l & 15;

    int start = g_rowstart[node];
    int n = g_cnt[node];
    float di = g_dinv[node];
    const uint2* y2p = reinterpret_cast<const uint2*>(g_yh);  // 8B = 4 halves

    float4 acc = make_float4(0.f, 0.f, 0.f, 0.f);
    if (half == 0) {   // self loop: y'[node]
        uint2 u = y2p[(size_t)node * 16 + chunk];
        float2 a = __half22float2(u32_to_h2(u.x));
        float2 c = __half22float2(u32_to_h2(u.y));
        acc.x = a.x; acc.y = a.y; acc.z = c.x; acc.w = c.y;
    }

    for (int base = 0; base < n; base += 32) {
        int idx = base + l;
        int s = 0;
        if (idx < n) s = g_ssrc[start + idx];    // coalesced
        int m = n - base; if (m > 32) m = 32;
        int jmax = (m + 1) >> 1;
#pragma unroll 4
        for (int j = 0; j < jmax; j++) {
            int myj = 2 * j + half;              // even -> half0, odd -> half1
            int sj = __shfl_sync(0xffffffffu, s, myj);
            if (myj < m) {
                uint2 u = y2p[(size_t)sj * 16 + chunk];
                float2 a = __half22float2(u32_to_h2(u.x));
                float2 c = __half22float2(u32_to_h2(u.y));
                acc.x += a.x; acc.y += a.y; acc.z += c.x; acc.w += c.y;
            }
        }
    }

    // merge half-warps
    acc.x += __shfl_xor_sync(0xffffffffu, acc.x, 16);
    acc.y += __shfl_xor_sync(0xffffffffu, acc.y, 16);
    acc.z += __shfl_xor_sync(0xffffffffu, acc.z, 16);
    acc.w += __shfl_xor_sync(0xffffffffu, acc.w, 16);

    // redistribute: lane l takes logits [2l, 2l+1] from chunk l>>1
    int srcl = l >> 1;
    float4 v;
    v.x = __shfl_sync(0xffffffffu, acc.x, srcl);
    v.y = __shfl_sync(0xffffffffu, acc.y, srcl);
    v.z = __shfl_sync(0xffffffffu, acc.z, srcl);
    v.w = __shfl_sync(0xffffffffu, acc.w, srcl);
    float2 mine = (l & 1) ? make_float2(v.z, v.w) : make_float2(v.x, v.y);

    const float2* b2 = reinterpret_cast<const float2*>(b);
    float2 bb = b2[l];
    float l0 = mine.x * di + bb.x;
    float l1 = mine.y * di + bb.y;

    float m = fmaxf(l0, l1);
#pragma unroll
    for (int o = 16; o; o >>= 1) m = fmaxf(m, __shfl_xor_sync(0xffffffffu, m, o));
    float s = __expf(l0 - m) + __expf(l1 - m);
#pragma unroll
    for (int o = 16; o; o >>= 1) s += __shfl_xor_sync(0xffffffffu, s, o);
    float lse = m + __logf(s);

    reinterpret_cast<float2*>(out + (size_t)node * NC)[l] = make_float2(l0 - lse, l1 - lse);
}

// ---------------------------------------------------------------------------
extern "C" void kernel_launch(void* const* d_in, const int* in_sizes, int n_in,
                              void* d_out, int out_size) {
    const float* x  = (const float*)d_in[0];
    const int*   ei = (const int*)d_in[1];
    const float* W  = (const float*)d_in[2];
    const float* b  = (const float*)d_in[3];
    float* out = (float*)d_out;

    const int* src = ei;        // edge_index[0]
    const int* dst = ei + NE;   // edge_index[1]

    if (!g_side) {
        cudaStreamCreateWithFlags(&g_side, cudaStreamNonBlocking);
        cudaEventCreateWithFlags(&g_evFork, cudaEventDisableTiming);
        cudaEventCreateWithFlags(&g_evDinv, cudaEventDisableTiming);
        cudaEventCreateWithFlags(&g_evJoin, cudaEventDisableTiming);
    }

    // Fork: gemm on side stream (depends only on x, W)
    cudaEventRecord(g_evFork, 0);
    cudaStreamWaitEvent(g_side, g_evFork, 0);
    gemm3_kernel<<<(NN + 255) / 256, 128, 0, g_side>>>(x, W);

    // Main: histogram then dinv (dinv needs only the histogram)
    zero_kernel<<<(NN + 255) / 256, 256>>>();
    hist_kernel<<<(NE + 255) / 256, 256>>>(dst);
    dinv_kernel<<<(NN + 255) / 256, 256>>>();
    cudaEventRecord(g_evDinv, 0);

    // Side: after gemm AND dinv -> scale y in place; record join
    cudaStreamWaitEvent(g_side, g_evDinv, 0);
    scale_kernel<<<(NN * NC / 8 + 255) / 256, 256, 0, g_side>>>();
    cudaEventRecord(g_evJoin, g_side);

    // Main: scans + scatter (overlaps gemm+scale)
    scan_a_kernel<<<SCAN_BLK, 1024>>>();
    scan_c_kernel<<<(NN + 255) / 256, 256>>>();
    scatter_kernel<<<(NE + 255) / 256, 256>>>(src, dst);

    // Join, then fused gather + softmax
    cudaStreamWaitEvent(0, g_evJoin, 0);
    gather_out_kernel<<<(NN * 32 + 255) / 256, 256>>>(b, out);
}

// round 17
// speedup vs baseline: 1.0012x; 1.0012x over previous
#include <cuda_runtime.h>
#include <cuda_fp16.h>
#include <cstdint>

#define NN 100000
#define NE 1600000
#define DF 128
#define NC 64
#define SCAN_BLK 98   // ceil(100000/1024)

// Scratch (__device__ globals per allocation-free rule)
__device__ __half g_yh[NN * NC];    // y then y' = y*dinv, fp16 (12.8MB)
__device__ float g_dinv[NN];
__device__ int   g_cnt[NN];         // edge-dst histogram (deg - 1)
__device__ int   g_incl[NN];        // inclusive scan within 1024-chunk
__device__ int   g_bsum[128];       // per-chunk sums
__device__ int   g_rowstart[NN];    // CSR row pointer (exclusive prefix)
__device__ int   g_cursor[NN];      // scatter cursors
__device__ int   g_ssrc[NE];        // edge sources sorted by dst

// Streams/events (lazy init on first call = correctness run, pre-capture)
static cudaStream_t g_side = nullptr;
static cudaEvent_t g_evFork = nullptr, g_evDinv = nullptr, g_evJoin = nullptr;
static void* g_cnt_ptr = nullptr;

__device__ __forceinline__ uint32_t smem_to_u32(const void* p) {
    uint32_t a;
    asm("{ .reg .u64 t; cvta.to.shared.u64 t, %1; cvt.u32.u64 %0, t; }"
        : "=r"(a) : "l"(p));
    return a;
}
__device__ __forceinline__ uint32_t h2_to_u32(__half2 h) {
    return *reinterpret_cast<uint32_t*>(&h);
}
__device__ __forceinline__ __half2 u32_to_h2(uint32_t u) {
    return *reinterpret_cast<__half2*>(&u);
}

// ---------------------------------------------------------------------------
// 2) histogram over edge destinations
// ---------------------------------------------------------------------------
__global__ void hist_kernel(const int* __restrict__ dst) {
    int e = blockIdx.x * blockDim.x + threadIdx.x;
    if (e < NE) atomicAdd(&g_cnt[dst[e]], 1);
}

// 3a) inclusive scan within each 1024-chunk (warp-shfl) + dinv (fused)
__global__ __launch_bounds__(1024) void scan_a_kernel() {
    __shared__ int wsum[32];
    int t = threadIdx.x;
    int lane = t & 31, wid = t >> 5;
    int gid = blockIdx.x * 1024 + t;
    int v = (gid < NN) ? g_cnt[gid] : 0;
    if (gid < NN) g_dinv[gid] = rsqrtf((float)v + 1.0f);   // fused dinv
    int inc = v;
#pragma unroll
    for (int off = 1; off < 32; off <<= 1) {
        int u = __shfl_up_sync(0xffffffffu, inc, off);
        if (lane >= off) inc += u;
    }
    if (lane == 31) wsum[wid] = inc;
    __syncthreads();
    if (wid == 0) {
        int s2 = wsum[lane];
#pragma unroll
        for (int off = 1; off < 32; off <<= 1) {
            int u = __shfl_up_sync(0xffffffffu, s2, off);
            if (lane >= off) s2 += u;
        }
        wsum[lane] = s2;
    }
    __syncthreads();
    if (wid > 0) inc += wsum[wid - 1];
    if (gid < NN) g_incl[gid] = inc;
    if (t == 1023) g_bsum[blockIdx.x] = inc;
}

// 3b) finalize (fused chunk-sum prefix): row_start, cursor
__global__ __launch_bounds__(256) void scan_c_kernel() {
    __shared__ int sbase;
    int t = threadIdx.x;
    int bl = blockIdx.x >> 2;
    if (t < 32) {
        int acc = 0;
        for (int q = t; q < bl; q += 32) acc += g_bsum[q];
#pragma unroll
        for (int o = 16; o; o >>= 1) acc += __shfl_xor_sync(0xffffffffu, acc, o);
        if (t == 0) sbase = acc;
    }
    __syncthreads();
    int gid = blockIdx.x * 256 + t;
    if (gid >= NN) return;
    int c = g_cnt[gid];
    int rs = sbase + g_incl[gid] - c;
    g_rowstart[gid] = rs;
    g_cursor[gid] = rs;
}

// 4) scatter: sort edge sources by dst bucket
__global__ void scatter_kernel(const int* __restrict__ src,
                               const int* __restrict__ dst) {
    int e = blockIdx.x * blockDim.x + threadIdx.x;
    if (e >= NE) return;
    int d = dst[e];
    int pos = atomicAdd(&g_cursor[d], 1);
    g_ssrc[pos] = src[e];
}

// ---------------------------------------------------------------------------
// 5) GEMM: y[N,64] = x[N,128] @ W^T  (fma.rn.f32x2), epilogue converts to fp16
// ---------------------------------------------------------------------------
__global__ __launch_bounds__(128) void gemm3_kernel(const float* __restrict__ x,
                                                    const float* __restrict__ W) {
    __shared__ float Wsm[DF * NC];   // [k][c], 32KB
    __shared__ float Xs[256 * 12];   // 12KB staged x
    int t = threadIdx.x;

    for (int i = t; i < DF * NC; i += 128) {
        int k = i >> 6, c = i & 63;
        Wsm[k * NC + c] = W[c * DF + k];
    }

    int w = t >> 5, l = t & 31;
    int ch = w & 1, pair = w >> 1;
    int rbase = blockIdx.x * 256;
    uint32_t w_base = smem_to_u32(Wsm) + (uint32_t)ch * 128;

    unsigned long long acc[4][16];
#pragma unroll
    for (int rr = 0; rr < 4; rr++)
#pragma unroll
        for (int q = 0; q < 16; q++) acc[rr][q] = 0ULL;

    const float4* x4 = reinterpret_cast<const float4*>(x);

    float4 pre[4];
#pragma unroll
    for (int i2 = 0; i2 < 4; i2++) {
        int idx = t + i2 * 128;
        int row = idx >> 1, half = idx & 1;
        int gr = rbase + row;
        pre[i2] = (gr < NN) ? x4[(size_t)gr * 32 + half]
                            : make_float4(0.f, 0.f, 0.f, 0.f);
    }

    for (int cc = 0; cc < 16; cc++) {
#pragma unroll
        for (int i2 = 0; i2 < 4; i2++) {
            int idx = t + i2 * 128;
            int row = idx >> 1, half = idx & 1;
            *reinterpret_cast<float4*>(Xs + row * 12 + half * 4) = pre[i2];
        }
        __syncthreads();

        if (cc < 15) {
#pragma unroll
            for (int i2 = 0; i2 < 4; i2++) {
                int idx = t + i2 * 128;
                int row = idx >> 1, half = idx & 1;
                int gr = rbase + row;
                pre[i2] = (gr < NN) ? x4[(size_t)gr * 32 + (cc + 1) * 2 + half]
                                    : make_float4(0.f, 0.f, 0.f, 0.f);
            }
        }

        float af[4][8];
#pragma unroll
        for (int rr = 0; rr < 4; rr++) {
            int rl = pair * 128 + 32 * rr + l;
            float4 v0 = *reinterpret_cast<const float4*>(Xs + rl * 12);
            float4 v1 = *reinterpret_cast<const float4*>(Xs + rl * 12 + 4);
            af[rr][0] = v0.x; af[rr][1] = v0.y; af[rr][2] = v0.z; af[rr][3] = v0.w;
            af[rr][4] = v1.x; af[rr][5] = v1.y; af[rr][6] = v1.z; af[rr][7] = v1.w;
        }

#pragma unroll
        for (int k = 0; k < 8; k++) {
            unsigned long long bm[4];
#pragma unroll
            for (int rr = 0; rr < 4; rr++)
                asm("mov.b64 %0, {%1, %1};" : "=l"(bm[rr]) : "f"(af[rr][k]));
            uint32_t rowa = w_base + (uint32_t)(cc * 8 + k) * (NC * 4);
#pragma unroll
            for (int q = 0; q < 8; q++) {
                unsigned long long w0, w1;
                asm("ld.shared.v2.b64 {%0, %1}, [%2];"
                    : "=l"(w0), "=l"(w1) : "r"(rowa + q * 16));
#pragma unroll
                for (int rr = 0; rr < 4; rr++) {
                    asm("fma.rn.f32x2 %0, %1, %2, %0;" : "+l"(acc[rr][2*q])   : "l"(bm[rr]), "l"(w0));
                    asm("fma.rn.f32x2 %0, %1, %2, %0;" : "+l"(acc[rr][2*q+1]) : "l"(bm[rr]), "l"(w1));
                }
            }
        }
        __syncthreads();
    }

#pragma unroll
    for (int rr = 0; rr < 4; rr++) {
        int r = rbase + pair * 128 + 32 * rr + l;
        if (r >= NN) continue;
        uint4* yo = reinterpret_cast<uint4*>(
            reinterpret_cast<char*>(g_yh) + (size_t)r * (NC * 2) + ch * 64);
#pragma unroll
        for (int q = 0; q < 4; q++) {
            float2 f0, f1, f2, f3;
            asm("mov.b64 {%0, %1}, %2;" : "=f"(f0.x), "=f"(f0.y) : "l"(acc[rr][4*q]));
            asm("mov.b64 {%0, %1}, %2;" : "=f"(f1.x), "=f"(f1.y) : "l"(acc[rr][4*q+1]));
            asm("mov.b64 {%0, %1}, %2;" : "=f"(f2.x), "=f"(f2.y) : "l"(acc[rr][4*q+2]));
            asm("mov.b64 {%0, %1}, %2;" : "=f"(f3.x), "=f"(f3.y) : "l"(acc[rr][4*q+3]));
            uint4 o;
            o.x = h2_to_u32(__floats2half2_rn(f0.x, f0.y));
            o.y = h2_to_u32(__floats2half2_rn(f1.x, f1.y));
            o.z = h2_to_u32(__floats2half2_rn(f2.x, f2.y));
            o.w = h2_to_u32(__floats2half2_rn(f3.x, f3.y));
            yo[q] = o;
        }
    }
}

// ---------------------------------------------------------------------------
// 5b) scale pass: y' = y * dinv[row]  (fp32 math, fp16 storage)
// ---------------------------------------------------------------------------
__global__ __launch_bounds__(256) void scale_kernel() {
    int i = blockIdx.x * blockDim.x + threadIdx.x;
    if (i >= NN * NC / 8) return;
    float d = g_dinv[i >> 3];
    uint4* p = reinterpret_cast<uint4*>(g_yh) + i;
    uint4 u = *p;
    float2 a = __half22float2(u32_to_h2(u.x));
    float2 b = __half22float2(u32_to_h2(u.y));
    float2 c = __half22float2(u32_to_h2(u.z));
    float2 e = __half22float2(u32_to_h2(u.w));
    u.x = h2_to_u32(__floats2half2_rn(a.x * d, a.y * d));
    u.y = h2_to_u32(__floats2half2_rn(b.x * d, b.y * d));
    u.z = h2_to_u32(__floats2half2_rn(c.x * d, c.y * d));
    u.w = h2_to_u32(__floats2half2_rn(e.x * d, e.y * d));
    *p = u;
}

// ---------------------------------------------------------------------------
// 6) fused gather + log_softmax: warp per node, lane owns classes [2l, 2l+1].
//    Per edge: 1 shfl + 1 full-warp 128B-line gather. No half-split/merge.
// ---------------------------------------------------------------------------
__global__ __launch_bounds__(256) void gather_out_kernel(const float* __restrict__ b,
                                                         float* __restrict__ out) {
    int node = (blockIdx.x * 256 + threadIdx.x) >> 5;
    int l = threadIdx.x & 31;
    if (node >= NN) return;

    int start = g_rowstart[node];
    int n = g_cnt[node];
    float di = g_dinv[node];
    const uint32_t* yw = reinterpret_cast<const uint32_t*>(g_yh);  // 4B = 2 halves

    float a0, a1;
    {   // self loop: y'[node]
        float2 f = __half22float2(u32_to_h2(yw[(size_t)node * 32 + l]));
        a0 = f.x; a1 = f.y;
    }

    for (int base = 0; base < n; base += 32) {
        int idx = base + l;
        int s = (idx < n) ? g_ssrc[start + idx] : 0;   // coalesced
        int m = n - base; if (m > 32) m = 32;
        int j = 0;
        for (; j + 4 <= m; j += 4) {
            int s0 = __shfl_sync(0xffffffffu, s, j);
            int s1 = __shfl_sync(0xffffffffu, s, j + 1);
            int s2 = __shfl_sync(0xffffffffu, s, j + 2);
            int s3 = __shfl_sync(0xffffffffu, s, j + 3);
            uint32_t u0 = yw[(size_t)s0 * 32 + l];
            uint32_t u1 = yw[(size_t)s1 * 32 + l];
            uint32_t u2 = yw[(size_t)s2 * 32 + l];
            uint32_t u3 = yw[(size_t)s3 * 32 + l];
            float2 f0 = __half22float2(u32_to_h2(u0));
            float2 f1 = __half22float2(u32_to_h2(u1));
            float2 f2 = __half22float2(u32_to_h2(u2));
            float2 f3 = __half22float2(u32_to_h2(u3));
            a0 += f0.x + f1.x + f2.x + f3.x;
            a1 += f0.y + f1.y + f2.y + f3.y;
        }
        for (; j < m; j++) {
            int sj = __shfl_sync(0xffffffffu, s, j);
            float2 f = __half22float2(u32_to_h2(yw[(size_t)sj * 32 + l]));
            a0 += f.x; a1 += f.y;
        }
    }

    // logits for classes 2l, 2l+1
    const float2* b2 = reinterpret_cast<const float2*>(b);
    float2 bb = b2[l];
    float l0 = a0 * di + bb.x;
    float l1 = a1 * di + bb.y;

    float m = fmaxf(l0, l1);
#pragma unroll
    for (int o = 16; o; o >>= 1) m = fmaxf(m, __shfl_xor_sync(0xffffffffu, m, o));
    float s = __expf(l0 - m) + __expf(l1 - m);
#pragma unroll
    for (int o = 16; o; o >>= 1) s += __shfl_xor_sync(0xffffffffu, s, o);
    float lse = m + __logf(s);

    reinterpret_cast<float2*>(out + (size_t)node * NC)[l] = make_float2(l0 - lse, l1 - lse);
}

// ---------------------------------------------------------------------------
extern "C" void kernel_launch(void* const* d_in, const int* in_sizes, int n_in,
                              void* d_out, int out_size) {
    const float* x  = (const float*)d_in[0];
    const int*   ei = (const int*)d_in[1];
    const float* W  = (const float*)d_in[2];
    const float* b  = (const float*)d_in[3];
    float* out = (float*)d_out;

    const int* src = ei;        // edge_index[0]
    const int* dst = ei + NE;   // edge_index[1]

    if (!g_side) {
        cudaStreamCreateWithFlags(&g_side, cudaStreamNonBlocking);
        cudaEventCreateWithFlags(&g_evFork, cudaEventDisableTiming);
        cudaEventCreateWithFlags(&g_evDinv, cudaEventDisableTiming);
        cudaEventCreateWithFlags(&g_evJoin, cudaEventDisableTiming);
        cudaGetSymbolAddress(&g_cnt_ptr, g_cnt);
    }

    // Fork: gemm on side stream (depends only on x, W)
    cudaEventRecord(g_evFork, 0);
    cudaStreamWaitEvent(g_side, g_evFork, 0);
    gemm3_kernel<<<(NN + 255) / 256, 128, 0, g_side>>>(x, W);

    // Main: zero (memset node) -> histogram -> scan_a (computes dinv too)
    cudaMemsetAsync(g_cnt_ptr, 0, NN * sizeof(int), 0);
    hist_kernel<<<(NE + 255) / 256, 256>>>(dst);
    scan_a_kernel<<<SCAN_BLK, 1024>>>();
    cudaEventRecord(g_evDinv, 0);

    // Side: after gemm AND dinv -> scale y in place; record join
    cudaStreamWaitEvent(g_side, g_evDinv, 0);
    scale_kernel<<<(NN * NC / 8 + 255) / 256, 256, 0, g_side>>>();
    cudaEventRecord(g_evJoin, g_side);

    // Main: finalize scan + scatter (overlaps gemm+scale)
    scan_c_kernel<<<(NN + 255) / 256, 256>>>();
    scatter_kernel<<<(NE + 255) / 256, 256>>>(src, dst);

    // Join, then fused gather + softmax
    cudaStreamWaitEvent(0, g_evJoin, 0);
    gather_out_kernel<<<(NN * 32 + 255) / 256, 256>>>(b, out);
}